// round 6
// baseline (speedup 1.0000x reference)
#include <cuda_runtime.h>
#include <cuda_bf16.h>
#include <cstdint>

// SegEncodeLoss round 6: bulk-async streaming, fine-grained scheduling.
// r5 at grid=256 lost ~14% to CTA<->SM imbalance (108 SMs x 8 bands vs
// 40 x 4) plus ring bubbles. Now: 1024 CTAs x exactly 1 band (128KB) each,
// 2x16KB ring (8 chunks of 4 rows), smem ~33KB -> 6 CTAs/SM resident and
// work-stealing backfill; ceil(1024/148)=7 vs 6.92 mean -> ~1% imbalance.

constexpr int Cc      = 19;
constexpr int NBLK    = 32768;          // tiles
constexpr int NCTA    = 1024;           // 1 band (32 tiles) per CTA
constexpr int CPB     = 8;              // chunks per band
constexpr int CHUNK_B = 16384;          // 4 rows * 4KB

__device__ float    g_part[NCTA];
__device__ unsigned g_count = 0;        // self-resets via atomicInc wrap

__device__ __forceinline__ uint32_t smem_u32(const void* p) {
    uint32_t a;
    asm("{ .reg .u64 t; cvta.to.shared.u64 t, %1; cvt.u32.u64 %0, t; }"
        : "=r"(a) : "l"(p));
    return a;
}
__device__ __forceinline__ void mbar_init(uint32_t mbar, uint32_t cnt) {
    asm volatile("mbarrier.init.shared.b64 [%0], %1;" :: "r"(mbar), "r"(cnt) : "memory");
}
__device__ __forceinline__ void mbar_expect_tx(uint32_t mbar, uint32_t bytes) {
    asm volatile("mbarrier.arrive.expect_tx.shared.b64 _, [%0], %1;"
                 :: "r"(mbar), "r"(bytes) : "memory");
}
__device__ __forceinline__ void bulk_g2s(uint32_t dst, const void* src,
                                         uint32_t bytes, uint32_t mbar) {
    asm volatile(
        "cp.async.bulk.shared::cta.global.mbarrier::complete_tx::bytes "
        "[%0], [%1], %2, [%3];"
        :: "r"(dst), "l"(src), "r"(bytes), "r"(mbar) : "memory");
}
__device__ __forceinline__ void mbar_wait(uint32_t mbar, uint32_t parity) {
    asm volatile(
        "{\n\t"
        ".reg .pred P;\n\t"
        "WL_%=:\n\t"
        "mbarrier.try_wait.parity.acquire.cta.shared::cta.b64 P, [%0], %1, 0x989680;\n\t"
        "@P bra.uni WD_%=;\n\t"
        "bra.uni WL_%=;\n\t"
        "WD_%=:\n\t"
        "}"
        :: "r"(mbar), "r"(parity) : "memory");
}
__device__ __forceinline__ float bce_logit(float x, float t) {
    return fmaxf(x, 0.0f) - x * t + log1pf(__expf(-fabsf(x)));
}

__global__ void __launch_bounds__(256) seg_bulk_kernel(
    const float* __restrict__ preds,
    const int*   __restrict__ targets,
    float*       __restrict__ out)
{
    extern __shared__ char smem[];
    int4*     buf      = reinterpret_cast<int4*>(smem);                 // 2 x 16KB
    uint64_t* mbar_mem = reinterpret_cast<uint64_t*>(smem + 2 * CHUNK_B);
    unsigned* s_mask   = reinterpret_cast<unsigned*>(smem + 2 * CHUNK_B + 64);   // 32
    float*    s_part   = reinterpret_cast<float*>(smem + 2 * CHUNK_B + 64 + 128);

    const int tid  = threadIdx.x;
    const int warp = tid >> 5;           // 8 warps; warp owns tiles 4w..4w+3
    const int lane = tid & 31;
    const uint32_t mb0 = smem_u32(&mbar_mem[0]);
    const uint32_t mb1 = smem_u32(&mbar_mem[1]);

    if (tid == 0) { mbar_init(mb0, 1); mbar_init(mb1, 1); }
    __syncthreads();

    const int  band = blockIdx.x;
    const char* src_base = reinterpret_cast<const char*>(targets)
                         + (size_t)band * CPB * CHUNK_B;

    // Prologue: fill both ring stages.
    if (tid == 0) {
        mbar_expect_tx(mb0, CHUNK_B);
        bulk_g2s(smem_u32(&buf[0]), src_base + 0 * CHUNK_B, CHUNK_B, mb0);
        mbar_expect_tx(mb1, CHUNK_B);
        bulk_g2s(smem_u32(&buf[CHUNK_B / 16]), src_base + 1 * CHUNK_B, CHUNK_B, mb1);
    }

    // Prefetch this warp's 4 logit rows (band is known at entry; overlaps TMA).
    float xr0 = 0, xr1 = 0, xr2 = 0, xr3 = 0;
    {
        const int n0 = band * 32 + warp * 4;
        if (lane < Cc) {
            xr0 = __ldg(&preds[(n0 + 0) * Cc + lane]);
            xr1 = __ldg(&preds[(n0 + 1) * Cc + lane]);
            xr2 = __ldg(&preds[(n0 + 2) * Cc + lane]);
            xr3 = __ldg(&preds[(n0 + 3) * Cc + lane]);
        }
    }

    unsigned m = 0u;
    for (int k = 0; k < CPB; k++) {
        const int s = k & 1;
        mbar_wait(s ? mb1 : mb0, (k >> 1) & 1);

        // Warp stripe: 512B columns [512w, 512w+512) = tiles 4w..4w+3.
        // 4 rows per chunk, contiguous LDS.128 per row: conflict-free.
        const int4* bb = buf + s * (CHUNK_B / 16) + warp * 32 + lane;
        #pragma unroll
        for (int r = 0; r < 4; r++) {
            int4 v = bb[r * 256];
            m |= (1u << v.x) | (1u << v.y) | (1u << v.z) | (1u << v.w);
        }
        __syncthreads();                          // all warps done with buf[s]

        if (k + 2 < CPB && tid == 0) {
            mbar_expect_tx(s ? mb1 : mb0, CHUNK_B);
            bulk_g2s(smem_u32(&buf[s * (CHUNK_B / 16)]),
                     src_base + (size_t)(k + 2) * CHUNK_B, CHUNK_B, s ? mb1 : mb0);
        }
    }

    // Band done: OR across the 8-lane group -> full per-tile mask.
    m |= __shfl_xor_sync(0xffffffffu, m, 1);
    m |= __shfl_xor_sync(0xffffffffu, m, 2);
    m |= __shfl_xor_sync(0xffffffffu, m, 4);
    if ((lane & 7) == 0) s_mask[warp * 4 + (lane >> 3)] = m;
    __syncthreads();

    float acc = 0.0f;
    if (lane < Cc) {
        const unsigned m0 = s_mask[warp * 4 + 0];
        const unsigned m1 = s_mask[warp * 4 + 1];
        const unsigned m2 = s_mask[warp * 4 + 2];
        const unsigned m3 = s_mask[warp * 4 + 3];
        acc += bce_logit(xr0, (float)((m0 >> lane) & 1u));
        acc += bce_logit(xr1, (float)((m1 >> lane) & 1u));
        acc += bce_logit(xr2, (float)((m2 >> lane) & 1u));
        acc += bce_logit(xr3, (float)((m3 >> lane) & 1u));
    }

    #pragma unroll
    for (int o = 16; o > 0; o >>= 1)
        acc += __shfl_down_sync(0xffffffffu, acc, o);
    if (lane == 0) s_part[warp] = acc;
    __syncthreads();
    if (warp != 0) return;

    float cs = (lane < 8) ? s_part[lane] : 0.0f;
    #pragma unroll
    for (int o = 4; o > 0; o >>= 1)
        cs += __shfl_down_sync(0xffffffffu, cs, o);

    int is_last = 0;
    if (lane == 0) {
        g_part[blockIdx.x] = cs;
        __threadfence();
        unsigned old = atomicInc(&g_count, NCTA - 1u);   // wraps: replay-safe
        is_last = (old == NCTA - 1u);
    }
    is_last = __shfl_sync(0xffffffffu, is_last, 0);
    if (!is_last) return;

    double sd = 0.0;
    for (int i = lane; i < NCTA; i += 32)
        sd += (double)__ldcg(&g_part[i]);
    #pragma unroll
    for (int o = 16; o > 0; o >>= 1)
        sd += __shfl_down_sync(0xffffffffu, sd, o);
    if (lane == 0)
        out[0] = (float)(sd / ((double)NBLK * (double)Cc));
}

extern "C" void kernel_launch(void* const* d_in, const int* in_sizes, int n_in,
                              void* d_out, int out_size) {
    const float* preds   = (const float*)d_in[0];
    const int*   targets = (const int*)d_in[1];
    float*       out     = (float*)d_out;

    const int smem_bytes = 2 * CHUNK_B + 64 + 128 + 64;
    cudaFuncSetAttribute(seg_bulk_kernel,
                         cudaFuncAttributeMaxDynamicSharedMemorySize, smem_bytes);
    seg_bulk_kernel<<<NCTA, 256, smem_bytes>>>(preds, targets, out);
}

// round 7
// speedup vs baseline: 1.0122x; 1.0122x over previous
#include <cuda_runtime.h>
#include <cuda_bf16.h>
#include <cstdint>

// SegEncodeLoss round 7: 4-stage bulk-async ring.
// r5/r6 lesson: the 2-stage ring is consumption-gated -> ~1 chunk in flight
// per CTA; achieved BW tracked chunk size (32KB:4.87 TB/s, 16KB:4.44).
// Fix: 4 stages x 16KB (66KB smem, 3 CTAs/SM). Steady state keeps ~3 chunks
// in flight per CTA (~144KB/SM outstanding >> ~30KB BW-delay product),
// while retaining the fine-grained 1024-band static schedule (~1% imbalance).

constexpr int Cc      = 19;
constexpr int NBLK    = 32768;          // tiles
constexpr int NCTA    = 1024;           // 1 band (32 tiles, 128KB) per CTA
constexpr int CPB     = 8;              // chunks per band
constexpr int CHUNK_B = 16384;          // 4 rows * 4KB
constexpr int STAGES  = 4;

__device__ float    g_part[NCTA];
__device__ unsigned g_count = 0;        // self-resets via atomicInc wrap

__device__ __forceinline__ uint32_t smem_u32(const void* p) {
    uint32_t a;
    asm("{ .reg .u64 t; cvta.to.shared.u64 t, %1; cvt.u32.u64 %0, t; }"
        : "=r"(a) : "l"(p));
    return a;
}
__device__ __forceinline__ void mbar_init(uint32_t mbar, uint32_t cnt) {
    asm volatile("mbarrier.init.shared.b64 [%0], %1;" :: "r"(mbar), "r"(cnt) : "memory");
}
__device__ __forceinline__ void mbar_expect_tx(uint32_t mbar, uint32_t bytes) {
    asm volatile("mbarrier.arrive.expect_tx.shared.b64 _, [%0], %1;"
                 :: "r"(mbar), "r"(bytes) : "memory");
}
__device__ __forceinline__ void bulk_g2s(uint32_t dst, const void* src,
                                         uint32_t bytes, uint32_t mbar) {
    asm volatile(
        "cp.async.bulk.shared::cta.global.mbarrier::complete_tx::bytes "
        "[%0], [%1], %2, [%3];"
        :: "r"(dst), "l"(src), "r"(bytes), "r"(mbar) : "memory");
}
__device__ __forceinline__ void mbar_wait(uint32_t mbar, uint32_t parity) {
    asm volatile(
        "{\n\t"
        ".reg .pred P;\n\t"
        "WL_%=:\n\t"
        "mbarrier.try_wait.parity.acquire.cta.shared::cta.b64 P, [%0], %1, 0x989680;\n\t"
        "@P bra.uni WD_%=;\n\t"
        "bra.uni WL_%=;\n\t"
        "WD_%=:\n\t"
        "}"
        :: "r"(mbar), "r"(parity) : "memory");
}
__device__ __forceinline__ float bce_logit(float x, float t) {
    return fmaxf(x, 0.0f) - x * t + log1pf(__expf(-fabsf(x)));
}

__global__ void __launch_bounds__(256) seg_bulk_kernel(
    const float* __restrict__ preds,
    const int*   __restrict__ targets,
    float*       __restrict__ out)
{
    extern __shared__ char smem[];
    int4*     buf      = reinterpret_cast<int4*>(smem);                  // 4 x 16KB
    uint64_t* mbar_mem = reinterpret_cast<uint64_t*>(smem + STAGES * CHUNK_B);
    unsigned* s_mask   = reinterpret_cast<unsigned*>(smem + STAGES * CHUNK_B + 64);
    float*    s_part   = reinterpret_cast<float*>(smem + STAGES * CHUNK_B + 64 + 128);

    const int tid  = threadIdx.x;
    const int warp = tid >> 5;           // 8 warps; warp owns tiles 4w..4w+3
    const int lane = tid & 31;

    uint32_t mb[STAGES];
    #pragma unroll
    for (int s = 0; s < STAGES; s++) mb[s] = smem_u32(&mbar_mem[s]);

    if (tid == 0) {
        #pragma unroll
        for (int s = 0; s < STAGES; s++) mbar_init(mb[s], 1);
    }
    __syncthreads();

    const int  band = blockIdx.x;
    const char* src_base = reinterpret_cast<const char*>(targets)
                         + (size_t)band * CPB * CHUNK_B;

    // Prologue: fill all four ring stages.
    if (tid == 0) {
        #pragma unroll
        for (int s = 0; s < STAGES; s++) {
            mbar_expect_tx(mb[s], CHUNK_B);
            bulk_g2s(smem_u32(&buf[s * (CHUNK_B / 16)]),
                     src_base + (size_t)s * CHUNK_B, CHUNK_B, mb[s]);
        }
    }

    // Prefetch this warp's 4 logit rows (overlaps the TMA stream).
    float xr0 = 0, xr1 = 0, xr2 = 0, xr3 = 0;
    {
        const int n0 = band * 32 + warp * 4;
        if (lane < Cc) {
            xr0 = __ldg(&preds[(n0 + 0) * Cc + lane]);
            xr1 = __ldg(&preds[(n0 + 1) * Cc + lane]);
            xr2 = __ldg(&preds[(n0 + 2) * Cc + lane]);
            xr3 = __ldg(&preds[(n0 + 3) * Cc + lane]);
        }
    }

    unsigned m = 0u;
    #pragma unroll
    for (int k = 0; k < CPB; k++) {
        const int s = k & (STAGES - 1);
        mbar_wait(mb[s], (k >> 2) & 1);

        // Warp stripe: 512B columns [512w, 512w+512) = tiles 4w..4w+3.
        // 4 rows per chunk, contiguous LDS.128 per row: conflict-free.
        const int4* bb = buf + s * (CHUNK_B / 16) + warp * 32 + lane;
        #pragma unroll
        for (int r = 0; r < 4; r++) {
            int4 v = bb[r * 256];
            m |= (1u << v.x) | (1u << v.y) | (1u << v.z) | (1u << v.w);
        }
        __syncthreads();                          // all warps done with buf[s]

        if (k + STAGES < CPB && tid == 0) {
            mbar_expect_tx(mb[s], CHUNK_B);
            bulk_g2s(smem_u32(&buf[s * (CHUNK_B / 16)]),
                     src_base + (size_t)(k + STAGES) * CHUNK_B, CHUNK_B, mb[s]);
        }
    }

    // Band done: OR across the 8-lane group -> full per-tile mask.
    m |= __shfl_xor_sync(0xffffffffu, m, 1);
    m |= __shfl_xor_sync(0xffffffffu, m, 2);
    m |= __shfl_xor_sync(0xffffffffu, m, 4);
    if ((lane & 7) == 0) s_mask[warp * 4 + (lane >> 3)] = m;
    __syncthreads();

    float acc = 0.0f;
    if (lane < Cc) {
        const unsigned m0 = s_mask[warp * 4 + 0];
        const unsigned m1 = s_mask[warp * 4 + 1];
        const unsigned m2 = s_mask[warp * 4 + 2];
        const unsigned m3 = s_mask[warp * 4 + 3];
        acc += bce_logit(xr0, (float)((m0 >> lane) & 1u));
        acc += bce_logit(xr1, (float)((m1 >> lane) & 1u));
        acc += bce_logit(xr2, (float)((m2 >> lane) & 1u));
        acc += bce_logit(xr3, (float)((m3 >> lane) & 1u));
    }

    #pragma unroll
    for (int o = 16; o > 0; o >>= 1)
        acc += __shfl_down_sync(0xffffffffu, acc, o);
    if (lane == 0) s_part[warp] = acc;
    __syncthreads();
    if (warp != 0) return;

    float cs = (lane < 8) ? s_part[lane] : 0.0f;
    #pragma unroll
    for (int o = 4; o > 0; o >>= 1)
        cs += __shfl_down_sync(0xffffffffu, cs, o);

    int is_last = 0;
    if (lane == 0) {
        g_part[blockIdx.x] = cs;
        __threadfence();
        unsigned old = atomicInc(&g_count, NCTA - 1u);   // wraps: replay-safe
        is_last = (old == NCTA - 1u);
    }
    is_last = __shfl_sync(0xffffffffu, is_last, 0);
    if (!is_last) return;

    double sd = 0.0;
    for (int i = lane; i < NCTA; i += 32)
        sd += (double)__ldcg(&g_part[i]);
    #pragma unroll
    for (int o = 16; o > 0; o >>= 1)
        sd += __shfl_down_sync(0xffffffffu, sd, o);
    if (lane == 0)
        out[0] = (float)(sd / ((double)NBLK * (double)Cc));
}

extern "C" void kernel_launch(void* const* d_in, const int* in_sizes, int n_in,
                              void* d_out, int out_size) {
    const float* preds   = (const float*)d_in[0];
    const int*   targets = (const int*)d_in[1];
    float*       out     = (float*)d_out;

    const int smem_bytes = STAGES * CHUNK_B + 64 + 128 + 64;
    cudaFuncSetAttribute(seg_bulk_kernel,
                         cudaFuncAttributeMaxDynamicSharedMemorySize, smem_bytes);
    seg_bulk_kernel<<<NCTA, 256, smem_bytes>>>(preds, targets, out);
}